// round 5
// baseline (speedup 1.0000x reference)
#include <cuda_runtime.h>
#include <cuda_bf16.h>
#include <cstdint>

#define BATCH     8192
#define NCLASSES  8192
#define NGROUPS   512
#define PAD       128          // >= max group size (Poisson(16); huge margin)

// Scratch: __device__ globals only (allocation is forbidden).
__device__ unsigned short g_perm_pad[NGROUPS * PAD]; // per-group column lists, sentinel=NCLASSES
__device__ int            g_iters[NGROUPS];          // ceil(cnt/8) uint4 iterations per group
__device__ int            g_cnt[NGROUPS];            // group sizes
__device__ int            g_slot[NGROUPS];           // slot -> group, sorted by size desc

// ---------------------------------------------------------------------------
// K1: build padded, stable per-group column lists + counts.
// 64 blocks x 256 threads; block stages seg into smem, 8 warps own 1 group each.
// ---------------------------------------------------------------------------
__global__ __launch_bounds__(256)
void k_perm(const int* __restrict__ seg) {
    __shared__ int sseg[NCLASSES];
    const int t = threadIdx.x;

    const int4* s4 = (const int4*)seg;
    int4*       d4 = (int4*)sseg;
    #pragma unroll
    for (int k = 0; k < (NCLASSES / 4) / 256; ++k)
        d4[t + k * 256] = s4[t + k * 256];
    __syncthreads();

    const int lane = t & 31;
    const int g    = blockIdx.x * 8 + (t >> 5);
    unsigned short* dst = g_perm_pad + g * PAD;

    int cnt = 0;
    #pragma unroll 4
    for (int c0 = 0; c0 < NCLASSES; c0 += 32) {
        const int s = sseg[c0 + lane];
        const unsigned m = __ballot_sync(0xffffffffu, s == g);
        if (s == g)
            dst[cnt + __popc(m & ((1u << lane) - 1u))] = (unsigned short)(c0 + lane);
        cnt += __popc(m);
    }
    for (int j = cnt + lane; j < PAD; j += 32)           // sentinel fill
        dst[j] = (unsigned short)NCLASSES;
    if (lane == 0) {
        g_iters[g] = (cnt + 7) >> 3;
        g_cnt[g]   = cnt;
    }
}

// ---------------------------------------------------------------------------
// K2: counting-sort groups by size (descending) -> g_slot.
// Balances per-lane gather work so warp-max ~= warp-mean. Assignment order
// does not affect output bits (per-group sum order is fixed by the perm list).
// ---------------------------------------------------------------------------
__global__ __launch_bounds__(NGROUPS)
void k_rank() {
    __shared__ int hist[PAD];
    __shared__ int base[PAD];
    __shared__ int off[PAD];
    const int t = threadIdx.x;
    if (t < PAD) { hist[t] = 0; off[t] = 0; }
    __syncthreads();
    const int c = g_cnt[t];
    atomicAdd(&hist[c], 1);
    __syncthreads();
    if (t == 0) {                         // descending exclusive prefix
        int run = 0;
        for (int v = PAD - 1; v >= 0; --v) { base[v] = run; run += hist[v]; }
    }
    __syncthreads();
    const int rank = base[c] + atomicAdd(&off[c], 1);
    g_slot[rank] = t;
}

// ---------------------------------------------------------------------------
// K3: hot kernel. Stage 2 rows interleaved as float2 (streaming loads), each
// thread gathers the columns of its *size-balanced* group with LDS.64 + packed
// f32x2 adds (4 chains), restage results in smem, coalesced output.
// ---------------------------------------------------------------------------
__global__ __launch_bounds__(512, 3)
void k_main(const float* __restrict__ x, float* __restrict__ out) {
    extern __shared__ float2 srow[];                 // NCLASSES+1 float2
    const int t = threadIdx.x;
    const size_t row0 = (size_t)blockIdx.x * 2;

    // Stage with evict-first loads (x is streamed once; keep L1 for perm).
    const float4* __restrict__ r0 = (const float4*)(x + row0 * NCLASSES);
    const float4* __restrict__ r1 = (const float4*)(x + (row0 + 1) * NCLASSES);
    #pragma unroll
    for (int k = 0; k < (NCLASSES / 4) / 512; ++k) {
        const int i = t + k * 512;
        const float4 a = __ldcs(&r0[i]);
        const float4 b = __ldcs(&r1[i]);
        srow[4 * i + 0] = make_float2(a.x, b.x);
        srow[4 * i + 1] = make_float2(a.y, b.y);
        srow[4 * i + 2] = make_float2(a.z, b.z);
        srow[4 * i + 3] = make_float2(a.w, b.w);
    }
    if (t == 0) srow[NCLASSES] = make_float2(0.f, 0.f);  // sentinel slot
    const int g = __ldg(&g_slot[t]);                     // balanced group pick
    __syncthreads();

    const uint4* __restrict__ pp = (const uint4*)(g_perm_pad + g * PAD);
    const int iters = __ldg(&g_iters[g]);

    const unsigned long long* s64 = (const unsigned long long*)srow;
    unsigned long long a0 = 0ull, a1 = 0ull, a2 = 0ull, a3 = 0ull;

    for (int it = 0; it < iters; ++it) {
        const uint4 v = __ldg(&pp[it]);
        unsigned idx;
        unsigned long long w;
        #define STEP(word, shift, A)                                   \
            idx = ((word) >> (shift)) & 0xFFFFu;                       \
            w = s64[idx];                                              \
            asm("add.rn.f32x2 %0, %1, %2;" : "=l"(A) : "l"(A), "l"(w));
        STEP(v.x,  0, a0) STEP(v.x, 16, a1)
        STEP(v.y,  0, a2) STEP(v.y, 16, a3)
        STEP(v.z,  0, a0) STEP(v.z, 16, a1)
        STEP(v.w,  0, a2) STEP(v.w, 16, a3)
        #undef STEP
    }
    unsigned long long s01, s23, s;
    asm("add.rn.f32x2 %0, %1, %2;" : "=l"(s01) : "l"(a0), "l"(a1));
    asm("add.rn.f32x2 %0, %1, %2;" : "=l"(s23) : "l"(a2), "l"(a3));
    asm("add.rn.f32x2 %0, %1, %2;" : "=l"(s)   : "l"(s01), "l"(s23));
    const float2 res = *(const float2*)&s;

    // Restage results so the global write stays coalesced.
    __syncthreads();
    srow[g] = res;
    __syncthreads();
    const float2 r = srow[t];
    out[row0 * NGROUPS + t]       = r.x;
    out[(row0 + 1) * NGROUPS + t] = r.y;
}

// ---------------------------------------------------------------------------
// Launch
// ---------------------------------------------------------------------------
extern "C" void kernel_launch(void* const* d_in, const int* in_sizes, int n_in,
                              void* d_out, int out_size) {
    const float* x   = (const float*)d_in[0];
    const int*   seg = (const int*)d_in[1];
    float*       out = (float*)d_out;

    const int smem_main = (NCLASSES + 1) * (int)sizeof(float2);  // 65544 B
    cudaFuncSetAttribute(k_main, cudaFuncAttributeMaxDynamicSharedMemorySize,
                         smem_main);

    k_perm<<<NGROUPS / 8, 256>>>(seg);
    k_rank<<<1, NGROUPS>>>();
    k_main<<<BATCH / 2, 512, smem_main>>>(x, out);
}

// round 6
// speedup vs baseline: 1.1841x; 1.1841x over previous
#include <cuda_runtime.h>
#include <cuda_bf16.h>
#include <cstdint>

#define BATCH     8192
#define NCLASSES  8192
#define NGROUPS   512
#define PAD       128            // >= max group size (Poisson(16); huge margin)

// smem float-index layout for k_main
#define ROWB      8208           // row1 base (byte off 32832, 16B aligned)
#define SENT_A    8192           // zero slot for row0 sentinel reads
#define SENT_B    (ROWB + 8192)  // 16400: zero slot for row1 sentinel reads
#define SMEM_FLOATS 16416        // padded total (65664 B) -> 3 blocks/SM

// Scratch: __device__ globals only (allocation is forbidden).
__device__ unsigned short g_perm_pad[NGROUPS * PAD]; // per-group columns, sentinel = NCLASSES (-> SENT slots)
__device__ int            g_iters[NGROUPS];          // ceil(cnt/8) uint4 iterations per group

// ---------------------------------------------------------------------------
// K1: build padded, stable per-group column lists. 64 blocks x 256 threads;
// block stages seg (32KB) to smem, 8 warps own one group each. The ballot
// scan is 4-way unrolled so the cnt dependency chain is 64 links, not 256.
// ---------------------------------------------------------------------------
__global__ __launch_bounds__(256)
void k_perm(const int* __restrict__ seg) {
    __shared__ int sseg[NCLASSES];
    const int t = threadIdx.x;

    const int4* s4 = (const int4*)seg;
    int4*       d4 = (int4*)sseg;
    #pragma unroll
    for (int k = 0; k < (NCLASSES / 4) / 256; ++k)
        d4[t + k * 256] = s4[t + k * 256];
    __syncthreads();

    const int      lane = t & 31;
    const int      g    = blockIdx.x * 8 + (t >> 5);
    const unsigned lm   = (1u << lane) - 1u;
    unsigned short* dst = g_perm_pad + g * PAD;

    int cnt = 0;
    for (int c0 = 0; c0 < NCLASSES; c0 += 128) {
        const int s0 = sseg[c0 +  0 + lane];
        const int s1 = sseg[c0 + 32 + lane];
        const int s2 = sseg[c0 + 64 + lane];
        const int s3 = sseg[c0 + 96 + lane];
        const unsigned m0 = __ballot_sync(0xffffffffu, s0 == g);
        const unsigned m1 = __ballot_sync(0xffffffffu, s1 == g);
        const unsigned m2 = __ballot_sync(0xffffffffu, s2 == g);
        const unsigned m3 = __ballot_sync(0xffffffffu, s3 == g);
        const int p0 = __popc(m0), p1 = __popc(m1), p2 = __popc(m2), p3 = __popc(m3);
        if (s0 == g) dst[cnt                + __popc(m0 & lm)] = (unsigned short)(c0 +  0 + lane);
        if (s1 == g) dst[cnt + p0           + __popc(m1 & lm)] = (unsigned short)(c0 + 32 + lane);
        if (s2 == g) dst[cnt + p0 + p1      + __popc(m2 & lm)] = (unsigned short)(c0 + 64 + lane);
        if (s3 == g) dst[cnt + p0 + p1 + p2 + __popc(m3 & lm)] = (unsigned short)(c0 + 96 + lane);
        cnt += p0 + p1 + p2 + p3;
    }
    for (int j = cnt + lane; j < PAD; j += 32)           // sentinel fill
        dst[j] = (unsigned short)NCLASSES;
    if (lane == 0) g_iters[g] = (cnt + 7) >> 3;
}

// ---------------------------------------------------------------------------
// K2: hot kernel. Two 32KB rows staged by cp.async.bulk (TMA path, single
// thread, mbarrier complete_tx) -> no staging LDG/STS wavefronts, no L1tex
// queue spread, no scoreboard stalls. Thread g gathers its group's columns
// with 2x LDS.32 per column (4 accumulator chains), coalesced output.
// ---------------------------------------------------------------------------
__global__ __launch_bounds__(512, 3)
void k_main(const float* __restrict__ x, float* __restrict__ out) {
    extern __shared__ float srow[];                  // [0,8192) row0, [8208,16400) row1
    __shared__ __align__(8) unsigned long long mbar;

    const int t = threadIdx.x;
    const size_t row0 = (size_t)blockIdx.x * 2;

    unsigned mbar_a, srow_a;
    asm("{ .reg .u64 a; cvta.to.shared.u64 a, %1; cvt.u32.u64 %0, a; }"
        : "=r"(mbar_a) : "l"(&mbar));
    asm("{ .reg .u64 a; cvta.to.shared.u64 a, %1; cvt.u32.u64 %0, a; }"
        : "=r"(srow_a) : "l"(srow));

    if (t == 0) {
        srow[SENT_A] = 0.f;                          // sentinel zero slots
        srow[SENT_B] = 0.f;
        asm volatile("mbarrier.init.shared.b64 [%0], 1;" :: "r"(mbar_a) : "memory");
    }
    __syncthreads();

    if (t == 0) {
        asm volatile("mbarrier.arrive.expect_tx.shared.b64 _, [%0], %1;"
                     :: "r"(mbar_a), "r"(2 * NCLASSES * 4) : "memory");
        const float* src = x + row0 * NCLASSES;
        asm volatile("cp.async.bulk.shared::cta.global.mbarrier::complete_tx::bytes [%0], [%1], %2, [%3];"
                     :: "r"(srow_a), "l"(src), "r"(NCLASSES * 4), "r"(mbar_a) : "memory");
        asm volatile("cp.async.bulk.shared::cta.global.mbarrier::complete_tx::bytes [%0], [%1], %2, [%3];"
                     :: "r"(srow_a + ROWB * 4), "l"(src + NCLASSES), "r"(NCLASSES * 4), "r"(mbar_a) : "memory");
    }

    // Overlap with the copy: fetch this thread's control data.
    const int g = t;
    const uint4* __restrict__ pp = (const uint4*)(g_perm_pad + g * PAD);
    const int iters = __ldg(&g_iters[g]);

    // Wait for both bulk copies (acquire orders TMA smem writes before LDS).
    {
        unsigned done = 0;
        while (!done) {
            asm volatile(
                "{\n\t.reg .pred P;\n\t"
                "mbarrier.try_wait.parity.acquire.cta.shared::cta.b64 P, [%1], 0, 0x989680;\n\t"
                "selp.b32 %0, 1, 0, P;\n\t}"
                : "=r"(done) : "r"(mbar_a) : "memory");
        }
    }

    float a0 = 0.f, a1 = 0.f, b0 = 0.f, b1 = 0.f;    // 2 chains per row
    for (int it = 0; it < iters; ++it) {
        const uint4 v = __ldg(&pp[it]);
        unsigned idx;
        #define STEP(word, shift, A, B)                \
            idx = ((word) >> (shift)) & 0xFFFFu;       \
            A += srow[idx];                            \
            B += srow[ROWB + idx];
        STEP(v.x,  0, a0, b0) STEP(v.x, 16, a1, b1)
        STEP(v.y,  0, a0, b0) STEP(v.y, 16, a1, b1)
        STEP(v.z,  0, a0, b0) STEP(v.z, 16, a1, b1)
        STEP(v.w,  0, a0, b0) STEP(v.w, 16, a1, b1)
        #undef STEP
    }

    out[row0 * NGROUPS + g]       = a0 + a1;          // coalesced: 512 floats/row
    out[(row0 + 1) * NGROUPS + g] = b0 + b1;
}

// ---------------------------------------------------------------------------
// Launch
// ---------------------------------------------------------------------------
extern "C" void kernel_launch(void* const* d_in, const int* in_sizes, int n_in,
                              void* d_out, int out_size) {
    const float* x   = (const float*)d_in[0];
    const int*   seg = (const int*)d_in[1];
    float*       out = (float*)d_out;

    const int smem_main = SMEM_FLOATS * (int)sizeof(float);   // 65664 B
    cudaFuncSetAttribute(k_main, cudaFuncAttributeMaxDynamicSharedMemorySize,
                         smem_main);

    k_perm<<<NGROUPS / 8, 256>>>(seg);
    k_main<<<BATCH / 2, 512, smem_main>>>(x, out);
}